// round 8
// baseline (speedup 1.0000x reference)
#include <cuda_runtime.h>
#include <cstdint>
#include <cstddef>

#define BB 1024
#define FF 4096
#define DD 32
#define NT 5             // n-tiles of 8: n 0-31 embed, 32 bias, 33-39 zero pad
#define MTILES 8
#define KSPLITS 32
#define K_PER_CTA 128
#define KC 32            // K per commit group
#define NCHUNK 4
#define A_STRIDE 132     // 128 k + 4 pad: conflict-free, 16B aligned
#define B_STRIDE 40
#define SMEM_FLOATS (128 * A_STRIDE + K_PER_CTA * B_STRIDE)   // 22016 -> 86 KB

__device__ float g_s[(size_t)BB * DD];   // accumulated s[row][d] (static zero; self-zeroing)
__device__ float g_b[(size_t)BB];        // accumulated bias_term[row]

__device__ __forceinline__ uint32_t smem_u32(const void* p) {
    uint32_t a;
    asm("{ .reg .u64 t; cvta.to.shared.u64 t, %1; cvt.u32.u64 %0, t; }" : "=r"(a) : "l"(p));
    return a;
}
__device__ __forceinline__ void cp16(uint32_t dst, const void* src) {
    asm volatile("cp.async.cg.shared.global [%0], [%1], 16;" :: "r"(dst), "l"(src));
}
__device__ __forceinline__ void cp4(uint32_t dst, const void* src) {
    asm volatile("cp.async.ca.shared.global [%0], [%1], 4;" :: "r"(dst), "l"(src));
}
__device__ __forceinline__ void cp_commit() { asm volatile("cp.async.commit_group;"); }
template <int N>
__device__ __forceinline__ void cp_wait() { asm volatile("cp.async.wait_group %0;" :: "n"(N)); }

// ---------------- GEMM: tf32 mma.sync, single-shot cp.async (max MLP) ----------------
__global__ void __launch_bounds__(256, 2)
fm_gemm(const float* __restrict__ data,
        const float* __restrict__ embed,
        const float* __restrict__ bias)
{
    extern __shared__ float sm[];
    float* As = sm;                       // [row][k] stride 132
    float* Bs = sm + 128 * A_STRIDE;      // [k][n]  stride 40

    const int t = threadIdx.x;
    const int w = t >> 5, lane = t & 31;
    const int g = lane >> 2, ctg = lane & 3;
    const int mtile = blockIdx.x & 7;
    const int kbase = (blockIdx.x >> 3) * K_PER_CTA;
    const float* arow0 = data + (size_t)(mtile * 128) * FF + kbase;

    // zero B pad columns (n=33..39, all 128 k-rows); cp.async never writes them
    for (int i = t; i < K_PER_CTA * 7; i += 256) {
        const int k = i / 7, n = 33 + (i - k * 7);
        Bs[k * B_STRIDE + n] = 0.f;
    }

    // ---- issue ALL loads up front, one commit group per 32-k chunk ----
    #pragma unroll
    for (int c = 0; c < NCHUNK; c++) {
        #pragma unroll
        for (int i = 0; i < 4; i++) {
            const int idx = t + i * 256;              // 1024 float4 of A per chunk
            const int row = idx >> 3, kq = (idx & 7) << 2;
            cp16(smem_u32(&As[row * A_STRIDE + c * KC + kq]),
                 arow0 + (size_t)row * FF + c * KC + kq);
        }
        const int k = t >> 3, q4 = (t & 7) << 2;      // 32 k-rows x 8 float4 of B
        cp16(smem_u32(&Bs[(c * KC + k) * B_STRIDE + q4]),
             embed + (size_t)(kbase + c * KC + k) * DD + q4);
        if (t < KC)
            cp4(smem_u32(&Bs[(c * KC + t) * B_STRIDE + 32]), bias + kbase + c * KC + t);
        cp_commit();
    }

    float acc[NT][4];
    #pragma unroll
    for (int nt = 0; nt < NT; nt++)
        #pragma unroll
        for (int j = 0; j < 4; j++) acc[nt][j] = 0.f;

    const float* Aw = &As[(w * 16) * A_STRIDE];

    #pragma unroll
    for (int ch = 0; ch < NCHUNK; ch++) {
        if (ch == 0)      cp_wait<3>();
        else if (ch == 1) cp_wait<2>();
        else if (ch == 2) cp_wait<1>();
        else              cp_wait<0>();
        __syncthreads();

        #pragma unroll
        for (int ks = 0; ks < 4; ks++) {
            const int k0 = ch * KC + ks * 8;
            const uint32_t a0 = __float_as_uint(Aw[g * A_STRIDE + k0 + ctg]);
            const uint32_t a1 = __float_as_uint(Aw[(g + 8) * A_STRIDE + k0 + ctg]);
            const uint32_t a2 = __float_as_uint(Aw[g * A_STRIDE + k0 + ctg + 4]);
            const uint32_t a3 = __float_as_uint(Aw[(g + 8) * A_STRIDE + k0 + ctg + 4]);
            #pragma unroll
            for (int nt = 0; nt < NT; nt++) {
                const uint32_t b0 = __float_as_uint(Bs[(k0 + ctg) * B_STRIDE + nt * 8 + g]);
                const uint32_t b1 = __float_as_uint(Bs[(k0 + ctg + 4) * B_STRIDE + nt * 8 + g]);
                asm volatile(
                    "mma.sync.aligned.m16n8k8.row.col.f32.tf32.tf32.f32 "
                    "{%0,%1,%2,%3}, {%4,%5,%6,%7}, {%8,%9}, {%0,%1,%2,%3};"
                    : "+f"(acc[nt][0]), "+f"(acc[nt][1]), "+f"(acc[nt][2]), "+f"(acc[nt][3])
                    : "r"(a0), "r"(a1), "r"(a2), "r"(a3), "r"(b0), "r"(b1));
            }
        }
    }

    // epilogue: one spread-address atomic pass; cols 33..39 are exact zeros (discard)
    const int mbase = mtile * 128 + w * 16;
    #pragma unroll
    for (int nt = 0; nt < NT; nt++) {
        #pragma unroll
        for (int j = 0; j < 4; j++) {
            const int n = nt * 8 + 2 * ctg + (j & 1);
            const int m = mbase + g + ((j >> 1) << 3);
            if (n < DD)
                atomicAdd(&g_s[(size_t)m * DD + n], acc[nt][j]);
            else if (n == DD)
                atomicAdd(&g_b[m], acc[nt][j]);
        }
    }
}

// ---------------- finisher: sigmoid + self-zero accumulators ----------------
__global__ void __launch_bounds__(256)
fm_finish(const float* __restrict__ gbias, float* __restrict__ out)
{
    const int w = threadIdx.x >> 5, lane = threadIdx.x & 31;
    const int row = blockIdx.x * 8 + w;

    const float s = g_s[(size_t)row * DD + lane];
    float t = s * s;
    if (lane == 0) t += g_b[row];

    #pragma unroll
    for (int o = 16; o; o >>= 1)
        t += __shfl_xor_sync(0xffffffffu, t, o);

    if (lane == 0) {
        out[row] = 1.0f / (1.0f + __expf(-(gbias[0] + t)));
        g_b[row] = 0.f;
    }
    g_s[(size_t)row * DD + lane] = 0.f;   // reset for next replay
}

extern "C" void kernel_launch(void* const* d_in, const int* in_sizes, int n_in,
                              void* d_out, int out_size)
{
    const float* data  = (const float*)d_in[0];
    const float* embed = (const float*)d_in[1];
    const float* bias  = (const float*)d_in[2];
    const float* gb    = (const float*)d_in[3];
    float* out = (float*)d_out;

    const int smem_bytes = SMEM_FLOATS * (int)sizeof(float);
    cudaFuncSetAttribute(fm_gemm, cudaFuncAttributeMaxDynamicSharedMemorySize, smem_bytes);

    fm_gemm<<<MTILES * KSPLITS, 256, smem_bytes>>>(data, embed, bias);
    fm_finish<<<BB / 8, 256>>>(gb, out);
}